// round 13
// baseline (speedup 1.0000x reference)
#include <cuda_runtime.h>
#include <cuda_bf16.h>

#define B_  64
#define Q_  900
#define T_  100
#define C_  256
#define INF_ 1e9f
#define QT  16    // q-rows per cost tile
#define NCH 57    // ceil(Q_/16); last chunk has 4 rows

// Transposed cost scratch [B, T, Q] for contiguous row access in Hungarian.
__device__ float g_costT[B_ * T_ * Q_];
// Per (b, chunk, target-row) packed partial min of RAW cost: [key:32 | col:32]
__device__ unsigned long long g_rowpart[B_ * NCH * T_];
// Per-batch completion counters (0 at launch start and launch end -> replay-safe)
__device__ int g_done[B_];

__device__ __forceinline__ unsigned int f32_orderable(float f) {
    unsigned int b = __float_as_uint(f);
    return (b & 0x80000000u) ? ~b : (b | 0x80000000u);
}

struct HungS {
    float v[Q_];            // first: 16B-aligned for float4 reads
    int   pred[Q_];
    int   y[Q_];
    int   x[T_];
    float rv[2][8];
    int   ri[2][8];
    int   col[T_];
    int   rmin[T_];
    int   freeRows[T_];
    int   s_nfree;
};
struct CostS {
    float slog[QT][257];
    float stile[QT][100];
    float stb[T_][4];
    int   slab[T_];
    float spb[QT][4];
};

// ---------------------------------------------------------------------------
// Fused kernel. blocks [0,64): Hungarian (waits on g_done[b]==NCH).
//               blocks [64, 64+B_*NCH): cost chunk (b, ch).
// ---------------------------------------------------------------------------
__global__ __launch_bounds__(256) void fused_kernel(
    const float* __restrict__ logits,   // [B,Q,C]
    const float* __restrict__ pboxes,   // [B,Q,4] cxcywh
    const int*   __restrict__ labels,   // [B,T]
    const float* __restrict__ tboxes,   // [B,T,4] cxcywh
    float* __restrict__ out)            // d_out
{
    __shared__ __align__(16) union { HungS h; CostS c; } sm;
    const int tid = threadIdx.x;

    if (blockIdx.x >= B_) {
        // =================== cost path (R12-proven) ===================
        const int bid2 = blockIdx.x - B_;
        const int b  = bid2 / NCH;
        const int ch = bid2 - b * NCH;
        const int q0 = ch * QT;
        const int qcnt = min(QT, Q_ - q0);
        CostS& S = sm.c;

        {
            const float* lg = logits + ((long)b * Q_ + q0) * C_;
            for (int i = tid * 4; i < qcnt * C_; i += 256 * 4) {
                float4 vv = *reinterpret_cast<const float4*>(lg + i);
                int r = i >> 8, c = i & 255;
                S.slog[r][c + 0] = vv.x; S.slog[r][c + 1] = vv.y;
                S.slog[r][c + 2] = vv.z; S.slog[r][c + 3] = vv.w;
            }
        }
        for (int i = tid; i < T_ * 4; i += 256)
            S.stb[i >> 2][i & 3] = tboxes[(long)b * T_ * 4 + i];
        for (int i = tid; i < T_; i += 256)
            S.slab[i] = labels[(long)b * T_ + i];
        for (int i = tid; i < qcnt * 4; i += 256)
            S.spb[i >> 2][i & 3] = pboxes[((long)b * Q_ + q0) * 4 + i];
        __syncthreads();

        for (int idx = tid; idx < qcnt * T_; idx += 256) {
            int qi = idx / T_;
            int t  = idx - qi * T_;
            float pcx = S.spb[qi][0], pcy = S.spb[qi][1], pw = S.spb[qi][2], ph = S.spb[qi][3];
            float tcx = S.stb[t][0],  tcy = S.stb[t][1],  tw = S.stb[t][2],  th = S.stb[t][3];

            float l1 = fabsf(pcx - tcx) + fabsf(pcy - tcy) + fabsf(pw - tw) + fabsf(ph - th);

            float ax0 = pcx - 0.5f * pw, ay0 = pcy - 0.5f * ph;
            float ax1 = pcx + 0.5f * pw, ay1 = pcy + 0.5f * ph;
            float bx0 = tcx - 0.5f * tw, by0 = tcy - 0.5f * th;
            float bx1 = tcx + 0.5f * tw, by1 = tcy + 0.5f * th;

            float areaA = (ax1 - ax0) * (ay1 - ay0);
            float areaB = (bx1 - bx0) * (by1 - by0);
            float ltx = fmaxf(ax0, bx0), lty = fmaxf(ay0, by0);
            float rbx = fminf(ax1, bx1), rby = fminf(ay1, by1);
            float iw = fmaxf(rbx - ltx, 0.f), ih = fmaxf(rby - lty, 0.f);
            float inter = iw * ih;
            float uni = areaA + areaB - inter;
            float iou = inter / uni;
            float ex0 = fminf(ax0, bx0), ey0 = fminf(ay0, by0);
            float ex1 = fmaxf(ax1, bx1), ey1 = fmaxf(ay1, by1);
            float enc = fmaxf(ex1 - ex0, 0.f) * fmaxf(ey1 - ey0, 0.f);
            float giou = iou - (enc - uni) / enc;

            float cval = -S.slog[qi][S.slab[t]] + l1 - giou;
            S.stile[qi][t] = cval;
            out[((long)(b * Q_ + q0 + qi)) * T_ + t] = cval;   // coalesced over t
        }
        __syncthreads();

        if (tid < T_) {
            float best = INF_; int bq = 0;
            for (int qi = 0; qi < qcnt; qi++) {
                float c = S.stile[qi][tid];
                if (c < best) { best = c; bq = q0 + qi; }
            }
            g_rowpart[((long)b * NCH + ch) * T_ + tid] =
                ((unsigned long long)f32_orderable(best) << 32) | (unsigned int)bq;
        }

        for (int idx = tid; idx < T_ * 4; idx += 256) {
            int t   = idx >> 2;
            int seg = idx & 3;
            if (seg * 4 < qcnt) {
                float4 vv = make_float4(S.stile[seg * 4 + 0][t], S.stile[seg * 4 + 1][t],
                                        S.stile[seg * 4 + 2][t], S.stile[seg * 4 + 3][t]);
                *reinterpret_cast<float4*>(
                    g_costT + ((long)b * T_ + t) * Q_ + q0 + seg * 4) = vv;
            }
        }

        // publish: all stores visible before the counter increment
        __threadfence();
        __syncthreads();
        if (tid == 0) atomicAdd(&g_done[b], 1);
        return;
    }

    // =================== Hungarian path (R12-proven) ===================
    const int b    = blockIdx.x;
    const int wid  = tid >> 5, lane = tid & 31;
    const float* CT = g_costT + (long)b * T_ * Q_;
    const bool owns = (tid < Q_ / 4);
    HungS& S = sm.h;

    for (int j = tid; j < Q_; j += 256) { S.v[j] = 0.f; S.y[j] = -1; }

    // wait for this batch's 57 cost chunks
    if (tid == 0) {
        volatile int* dp = &g_done[b];
        while (*dp < NCH) __nanosleep(128);
        __threadfence();
        g_done[b] = 0;                 // reset for next graph replay
    }
    __syncthreads();

    if (tid < T_) {
        const unsigned long long* rp = g_rowpart + (long)b * NCH * T_ + tid;
        unsigned long long m = rp[0];
        #pragma unroll
        for (int c = 1; c < NCH; c++) {
            unsigned long long pk = rp[(long)c * T_];
            if (pk < m) m = pk;
        }
        S.rmin[tid] = (int)(unsigned int)(m & 0xFFFFFFFFULL);
    }
    __syncthreads();

    if (tid == 0) {
        int nf = 0;
        for (int i = 0; i < T_; i++) {
            int j = S.rmin[i];
            if (S.y[j] < 0) { S.y[j] = i; S.x[i] = j; }
            else            { S.x[i] = -1; S.freeRows[nf++] = i; }
        }
        S.s_nfree = nf;
    }
    __syncthreads();
    const int nfree = S.s_nfree;

    for (int fi = 0; fi < nfree; fi++) {
        const int f = S.freeRows[fi];
        float4 d = make_float4(INF_, INF_, INF_, INF_);
        unsigned int scm = 0;
        int   i1 = f;
        float h  = 0.f;
        const float* crow = CT + (long)f * Q_;
        float mu; int jstar;
        int pp = 0;

        while (true) {
            float bv = INF_; int bj = 0x7fffffff;
            if (owns) {
                const int j0 = tid << 2;
                float4 cv = __ldg((const float4*)(crow) + tid);
                float4 vv = *((const float4*)S.v + tid);
                if (!(scm & 1u)) {
                    float nd = cv.x - vv.x - h;
                    if (nd < d.x) { d.x = nd; S.pred[j0 + 0] = i1; }
                    if (d.x < bv) { bv = d.x; bj = j0 + 0; }
                }
                if (!(scm & 2u)) {
                    float nd = cv.y - vv.y - h;
                    if (nd < d.y) { d.y = nd; S.pred[j0 + 1] = i1; }
                    if (d.y < bv) { bv = d.y; bj = j0 + 1; }
                }
                if (!(scm & 4u)) {
                    float nd = cv.z - vv.z - h;
                    if (nd < d.z) { d.z = nd; S.pred[j0 + 2] = i1; }
                    if (d.z < bv) { bv = d.z; bj = j0 + 2; }
                }
                if (!(scm & 8u)) {
                    float nd = cv.w - vv.w - h;
                    if (nd < d.w) { d.w = nd; S.pred[j0 + 3] = i1; }
                    if (d.w < bv) { bv = d.w; bj = j0 + 3; }
                }
            }
            // warp argmin: redux over orderable key, ballot picks lowest lane
            {
                unsigned int key = f32_orderable(bv);
                unsigned int mk  = __reduce_min_sync(0xffffffffu, key);
                unsigned int bal = __ballot_sync(0xffffffffu, key == mk);
                int src = __ffs(bal) - 1;
                bv = __shfl_sync(0xffffffffu, bv, src);
                bj = __shfl_sync(0xffffffffu, bj, src);
            }
            if (lane == 0) { S.rv[pp][wid] = bv; S.ri[pp][wid] = bj; }
            __syncthreads();                       // the ONLY barrier per iter

            mu = S.rv[pp][0]; jstar = S.ri[pp][0];
            #pragma unroll
            for (int k = 1; k < 8; k++) {
                float v2 = S.rv[pp][k]; int j2 = S.ri[pp][k];
                if (v2 < mu || (v2 == mu && j2 < jstar)) { mu = v2; jstar = j2; }
            }
            i1 = S.y[jstar];
            if (i1 < 0) break;

            if ((jstar >> 2) == tid) scm |= 1u << (jstar & 3);
            crow = CT + (long)i1 * Q_;
            h = __ldg(crow + jstar) - S.v[jstar] - mu;
            pp ^= 1;
        }
        __syncthreads();

        if (owns) {
            const int j0 = tid << 2;
            if (scm & 1u) S.v[j0 + 0] += d.x - mu;
            if (scm & 2u) S.v[j0 + 1] += d.y - mu;
            if (scm & 4u) S.v[j0 + 2] += d.z - mu;
            if (scm & 8u) S.v[j0 + 3] += d.w - mu;
        }

        if (tid == 0) {
            int j = jstar;
            while (true) {
                int i = S.pred[j];
                S.y[j] = i;
                int jn = S.x[i];
                S.x[i] = j;
                if (i == f) break;
                j = jn;
            }
        }
        __syncthreads();
    }

    for (int j = tid; j < Q_; j += 256) {
        int r = S.y[j];
        if (r >= 0) S.col[r] = j;
    }
    __syncthreads();

    if (tid < T_) {
        int c = S.col[tid];
        int r = 0;
        #pragma unroll 4
        for (int t2 = 0; t2 < T_; t2++) r += (S.col[t2] < c);
        const long base = (long)B_ * Q_ * T_;
        out[base + (long)b * T_ + r] = (float)c;                    // pred_idx
        out[base + (long)B_ * T_ + (long)b * T_ + r] = (float)tid;  // tgt_idx
    }
}

extern "C" void kernel_launch(void* const* d_in, const int* in_sizes, int n_in,
                              void* d_out, int out_size)
{
    const float* pred_logits = (const float*)d_in[0];
    const float* pred_boxes  = (const float*)d_in[1];
    const int*   tgt_labels  = (const int*)d_in[2];
    const float* tgt_boxes   = (const float*)d_in[3];
    float* out = (float*)d_out;

    fused_kernel<<<B_ + B_ * NCH, 256>>>(pred_logits, pred_boxes, tgt_labels,
                                         tgt_boxes, out);
}